// round 12
// baseline (speedup 1.0000x reference)
#include <cuda_runtime.h>
#include <cuda_bf16.h>
#include <mma.h>
#include <cstdint>

using namespace nvcuda;

#define NN 262144
#define DD 128
#define KK 512
#define GG 4096
#define TT 10

// output layout (float32, concatenated reference tuple)
#define OFF_CPRE   0
#define OFF_XPRE   (GG * TT)            // counter_pre
#define OFF_YPRE   (2 * GG * TT)
#define OFF_Z      (3 * GG * TT)
#define OFF_PCA    (OFF_Z + (size_t)NN * DD)
#define OFF_PX     (OFF_PCA + (size_t)GG * DD)

#define MARGIN_THRESH 0.01f

#define LDB 136                         // bf16 tile leading dim (elements)
#define LDS_STG 20                      // staging leading dim (floats)

#define BTILE_U4 4352                   // one code tile (bh+bl) in uint4s

// smem byte offsets (256-node CTA): [xh][xl][B][staging][c2][merge]
#define SM_XH   0
#define SM_XL   69632
#define SM_B    139264
#define SM_ST   208896                  // 8 warps x 16x20 floats = 10240
#define SM_C2   219136                  // 512 floats
#define SM_MG   221184                  // merge: 2x256x(v1,v2,idx) = 6144
#define SMEM_TC 227328

__device__ int   g_idx[NN];
__device__ int   g_seg[GG + 1];
__device__ float g_c2[KK];       // fast-path c2
__device__ float g_c2e[KK];      // reference-emulated c2 (sequential fp32, no fma)
__device__ float g_cbT[DD * KK]; // transposed causal codebook for coalesced refine
__device__ int   g_flag[NN];
__device__ int   g_nflag;
__device__ float g_x2f[NN];      // emulated x2 per flagged node (by flag position)
__device__ uint4 g_cbs[4][BTILE_U4];   // pre-split codebook tiles: [bh | bl] blocked layout

// ---------------- cp.async helpers ----------------
__device__ __forceinline__ void cpa16(uint32_t saddr, const void* gptr) {
    asm volatile("cp.async.cg.shared.global [%0], [%1], 16;"
                 :: "r"(saddr), "l"(gptr));
}
__device__ __forceinline__ void cpa_commit() {
    asm volatile("cp.async.commit_group;");
}
__device__ __forceinline__ void cpa_wait0() {
    asm volatile("cp.async.wait_group 0;");
}

// symmetric top-2 merge with first-index tie-break
__device__ __forceinline__ void comb2(float& v1, int& i1, float& v2,
                                      float ov1, int oi1, float ov2) {
    if (ov1 < v1 || (ov1 == v1 && oi1 < i1)) {
        v2 = fminf(v1, ov2);
        v1 = ov1; i1 = oi1;
    } else {
        v2 = fminf(v2, ov1);
    }
}

// ---------------- segment offsets via binary search (batch is sorted) ----------------
__global__ void seg_kernel(const int* __restrict__ bw, int n) {
    int g = blockIdx.x * blockDim.x + threadIdx.x;
    if (g == 0) g_nflag = 0;
    if (g > GG) return;
    bool is64 = (bw[n - 1] == 0) && (bw[n - 3] == 0);
    int lo = 0, hi = n;
    while (lo < hi) {
        int mid = (lo + hi) >> 1;
        int v = is64 ? bw[2 * mid] : bw[mid];
        if (v < g) lo = mid + 1; else hi = mid;
    }
    g_seg[g] = lo;
}

// ---------------- fast c2 + emulated c2 + transpose, fused ----------------
__global__ void prep_kernel(const float* __restrict__ cc) {
    int k = blockIdx.x * 8 + (threadIdx.x >> 5);
    int lane = threadIdx.x & 31;
    float v[4];
    float s = 0.f;
#pragma unroll
    for (int j = 0; j < 4; ++j) {
        v[j] = cc[k * DD + lane + 32 * j];
        s = fmaf(v[j], v[j], s);
        g_cbT[(lane + 32 * j) * KK + k] = v[j];
    }
#pragma unroll
    for (int o = 16; o; o >>= 1) s += __shfl_xor_sync(0xffffffffu, s, o);
    if (lane == 0) g_c2[k] = s;
    if (lane == 0) {
        const float* r = cc + (size_t)k * DD;
        float acc = 0.f;
        for (int d = 0; d < DD; ++d)
            acc = __fadd_rn(acc, __fmul_rn(r[d], r[d]));
        g_c2e[k] = acc;
    }
}

// split one 8-float chunk to packed bf16 hi/lo uint4s
__device__ __forceinline__ void split8(const float* f, uint4& H, uint4& L) {
    uint32_t hp[4], lp[4];
#pragma unroll
    for (int j = 0; j < 4; ++j) {
        __nv_bfloat16 h0 = __float2bfloat16(f[2 * j]);
        __nv_bfloat16 h1 = __float2bfloat16(f[2 * j + 1]);
        __nv_bfloat16 l0 = __float2bfloat16(f[2 * j]     - __bfloat162float(h0));
        __nv_bfloat16 l1 = __float2bfloat16(f[2 * j + 1] - __bfloat162float(h1));
        hp[j] = ((uint32_t)__bfloat16_as_ushort(h1) << 16) | __bfloat16_as_ushort(h0);
        lp[j] = ((uint32_t)__bfloat16_as_ushort(l1) << 16) | __bfloat16_as_ushort(l0);
    }
    H = make_uint4(hp[0], hp[1], hp[2], hp[3]);
    L = make_uint4(lp[0], lp[1], lp[2], lp[3]);
}

// ---------------- pre-split codebook tiles to gmem (blocked smem layout) ----------
__global__ __launch_bounds__(256) void prep_split_kernel(const float* __restrict__ cb) {
    const int kt = blockIdx.x;           // 4 tiles
    const int tid = threadIdx.x;
#pragma unroll
    for (int it = 0; it < 8; ++it) {
        int idx = it * 256 + tid;        // 0..2047
        int row = idx >> 4, ch = idx & 15;
        float f[8];
        const float4* p = (const float4*)(cb + (size_t)(kt * 128 + row) * DD) + ch * 2;
        float4 v0 = p[0], v1 = p[1];
        f[0]=v0.x; f[1]=v0.y; f[2]=v0.z; f[3]=v0.w; f[4]=v1.x; f[5]=v1.y; f[6]=v1.z; f[7]=v1.w;
        uint4 H, L;
        split8(f, H, L);
        int u4 = row * 17 + ch;          // 272B rows = 17 uint4
        g_cbs[kt][u4] = H;
        g_cbs[kt][2176 + u4] = L;
    }
}

// ---------------- HMMA argmin: 256 nodes/CTA, 64x64 warp tiles, staged scan ----------
__global__ __launch_bounds__(256) void argmin_tc(
    const float* __restrict__ x)
{
    extern __shared__ char smem[];
    __nv_bfloat16* xh  = (__nv_bfloat16*)(smem + SM_XH);
    __nv_bfloat16* xl  = (__nv_bfloat16*)(smem + SM_XL);
    __nv_bfloat16* bh  = (__nv_bfloat16*)(smem + SM_B);
    __nv_bfloat16* bl  = (__nv_bfloat16*)(smem + SM_B + 34816);
    float*         c2s = (float*)(smem + SM_C2);

    const int tid  = threadIdx.x;
    const int wid  = tid >> 5;
    const int lane = tid & 31;
    const int wm   = wid & 3;            // node block: rows 64*wm..
    const int wn   = wid >> 2;           // code block: cols 64*wn..
    const int nbase = blockIdx.x * 256;

    const uint32_t sb = (uint32_t)__cvta_generic_to_shared(smem + SM_B);

    // prefetch B tile 0 while converting X
    {
        const uint4* src = g_cbs[0];
#pragma unroll
        for (int i = 0; i < 17; ++i) {
            int idx = tid + 256 * i;
            cpa16(sb + idx * 16, src + idx);
        }
        cpa_commit();
    }

    // fill X (256 rows) bf16 hi/lo
#pragma unroll
    for (int it = 0; it < 16; ++it) {
        int idx = it * 256 + tid;        // 0..4095
        int row = idx >> 4, ch = idx & 15;
        const float4* p = (const float4*)(x + (size_t)(nbase + row) * DD) + ch * 2;
        float4 v0 = p[0], v1 = p[1];
        float f[8] = {v0.x, v0.y, v0.z, v0.w, v1.x, v1.y, v1.z, v1.w};
        uint4 H, L;
        split8(f, H, L);
        int eo = row * LDB + ch * 8;
        *(uint4*)((char*)xh + 2 * eo) = H;
        *(uint4*)((char*)xl + 2 * eo) = L;
    }
    for (int k = tid; k < KK; k += 256) c2s[k] = g_c2[k];

    // per-lane top-2 state for 4 m-blocks (node = wm*64 + i*16 + lane%16)
    float bv[4], bv2[4];
    int   bi[4];
#pragma unroll
    for (int i = 0; i < 4; ++i) { bv[i] = 3.4e38f; bv2[i] = 3.4e38f; bi[i] = 0x7fffffff; }

    float* stg = (float*)(smem + SM_ST) + wid * 320;   // 16 x 20 floats per warp
    const int srow = lane & 15;
    const int scb  = (lane >> 4) * 8;

    for (int kt = 0; kt < 4; ++kt) {
        cpa_wait0();
        __syncthreads();                 // B(kt) ready (X + c2 also covered on kt=0)

        wmma::fragment<wmma::accumulator, 16, 16, 16, float> acc[4][4];
#pragma unroll
        for (int i = 0; i < 4; ++i)
#pragma unroll
            for (int j = 0; j < 4; ++j) wmma::fill_fragment(acc[i][j], 0.f);

#pragma unroll
        for (int kk = 0; kk < 8; ++kk) {
            const int k0 = kk * 16;
            wmma::fragment<wmma::matrix_a, 16, 16, 16, __nv_bfloat16, wmma::row_major> ah[4], al[4];
            wmma::fragment<wmma::matrix_b, 16, 16, 16, __nv_bfloat16, wmma::col_major> bhf[4], blf[4];
#pragma unroll
            for (int i = 0; i < 4; ++i) {
                wmma::load_matrix_sync(ah[i], xh + (wm * 64 + i * 16) * LDB + k0, LDB);
                wmma::load_matrix_sync(al[i], xl + (wm * 64 + i * 16) * LDB + k0, LDB);
            }
#pragma unroll
            for (int j = 0; j < 4; ++j) {
                wmma::load_matrix_sync(bhf[j], bh + (wn * 64 + j * 16) * LDB + k0, LDB);
                wmma::load_matrix_sync(blf[j], bl + (wn * 64 + j * 16) * LDB + k0, LDB);
            }
#pragma unroll
            for (int i = 0; i < 4; ++i)
#pragma unroll
                for (int j = 0; j < 4; ++j) {
                    wmma::mma_sync(acc[i][j], ah[i], bhf[j], acc[i][j]);
                    wmma::mma_sync(acc[i][j], ah[i], blf[j], acc[i][j]);
                    wmma::mma_sync(acc[i][j], al[i], bhf[j], acc[i][j]);
                }
        }
        __syncthreads();                 // all warps done reading B(kt)

        if (kt < 3) {                    // prefetch next tile; copy overlaps the scan
            const uint4* src = g_cbs[kt + 1];
#pragma unroll
            for (int i = 0; i < 17; ++i) {
                int idx = tid + 256 * i;
                cpa16(sb + idx * 16, src + idx);
            }
            cpa_commit();
        }

        // staged scan: one 16x16 fragment at a time through the warp-private buffer
#pragma unroll
        for (int i = 0; i < 4; ++i) {
#pragma unroll
            for (int j = 0; j < 4; ++j) {
                wmma::store_matrix_sync(stg, acc[i][j], LDS_STG, wmma::mem_row_major);
                __syncwarp();
                const float4* p = (const float4*)(stg + srow * LDS_STG + scb);
                float4 v0 = p[0], v1 = p[1];
                float dv[8] = {v0.x, v0.y, v0.z, v0.w, v1.x, v1.y, v1.z, v1.w};
#pragma unroll
                for (int u = 0; u < 8; ++u) {
                    int k = kt * 128 + wn * 64 + j * 16 + scb + u;
                    float s = fmaf(-2.f, dv[u], c2s[k]);
                    if (s < bv[i])       { bv2[i] = bv[i]; bv[i] = s; bi[i] = k; }
                    else if (s < bv2[i]) { bv2[i] = s; }
                }
                __syncwarp();
            }
        }
    }

    // merge col-halves within lane-pairs (lane l <-> l+16 share row srow)
#pragma unroll
    for (int i = 0; i < 4; ++i) {
        float ov1 = __shfl_xor_sync(0xffffffffu, bv[i],  16);
        float ov2 = __shfl_xor_sync(0xffffffffu, bv2[i], 16);
        int   oi1 = __shfl_xor_sync(0xffffffffu, bi[i],  16);
        comb2(bv[i], bi[i], bv2[i], ov1, oi1, ov2);
    }

    // cross-warp (wn) merge via smem
    float* mg1 = (float*)(smem + SM_MG);          // [2][256]
    float* mg2 = mg1 + 512;
    int*   mgi = (int*)(mg2 + 512);
    if (lane < 16) {
#pragma unroll
        for (int i = 0; i < 4; ++i) {
            int node = wm * 64 + i * 16 + lane;
            mg1[wn * 256 + node] = bv[i];
            mg2[wn * 256 + node] = bv2[i];
            mgi[wn * 256 + node] = bi[i];
        }
    }
    __syncthreads();
    {
        float v1 = mg1[tid], v2 = mg2[tid];
        int   i1 = mgi[tid];
        comb2(v1, i1, v2, mg1[256 + tid], mgi[256 + tid], mg2[256 + tid]);
        int gn = nbase + tid;
        g_idx[gn] = i1;
        if (v2 - v1 < MARGIN_THRESH) {
            int pos = atomicAdd(&g_nflag, 1);
            g_flag[pos] = gn;
        }
    }
}

// ---------------- emulated x2 for flagged nodes (parallel, one thread/node) ----------
__global__ void x2pre_kernel(const float* __restrict__ x) {
    int nf = g_nflag;
    for (int j = blockIdx.x * 128 + threadIdx.x; j < nf; j += gridDim.x * 128) {
        const float* r = x + (size_t)g_flag[j] * DD;
        float acc = 0.f;
        for (int d = 0; d < DD; ++d)
            acc = __fadd_rn(acc, __fmul_rn(r[d], r[d]));
        g_x2f[j] = acc;
    }
}

// ---------------- near-tie refine: bit-emulate the reference's fp32 arithmetic --------
__global__ __launch_bounds__(128) void refine_kernel(const float* __restrict__ x)
{
    __shared__ float xsh[DD];
    __shared__ float bvs[128];
    __shared__ int   bis[128];
    const int tid = threadIdx.x;
    const int nflag = g_nflag;

    for (int f = blockIdx.x; f < nflag; f += gridDim.x) {
        int node = g_flag[f];
        xsh[tid] = x[(size_t)node * DD + tid];
        __syncthreads();
        float x2 = g_x2f[f];

        float bestv = 3.4e38f; int besti = 0x7fffffff;
#pragma unroll
        for (int j = 0; j < 4; ++j) {
            int k = j * 128 + tid;               // lane-consecutive k: coalesced
            float dot = 0.f;
            for (int d = 0; d < DD; ++d)
                dot = __fmaf_rn(xsh[d], g_cbT[d * KK + k], dot);
            float s = __fsub_rn(__fadd_rn(x2, g_c2e[k]), __fmul_rn(2.f, dot));
            if (s < bestv || (s == bestv && k < besti)) { bestv = s; besti = k; }
        }
        bvs[tid] = bestv; bis[tid] = besti;
        __syncthreads();
        for (int st = 64; st > 0; st >>= 1) {
            if (tid < st) {
                float v2 = bvs[tid + st]; int k2 = bis[tid + st];
                if (v2 < bvs[tid] || (v2 == bvs[tid] && k2 < bis[tid])) {
                    bvs[tid] = v2; bis[tid] = k2;
                }
            }
            __syncthreads();
        }
        if (tid == 0) g_idx[node] = bis[0];
        __syncthreads();
    }
}

// ---------------- z_nodes gather: out_z[i] = codebook[idx[i]] ----------------
__global__ void gather_kernel(const float* __restrict__ cb, float* __restrict__ outz) {
    int gid = blockIdx.x * 256 + threadIdx.x;   // over N*32 float4s
    int i = gid >> 5, q = gid & 31;
    int k = g_idx[i];
    ((float4*)outz)[(size_t)i * 32 + q] = ((const float4*)cb)[(size_t)k * 32 + q];
}

// ---------------- per-graph pooling + tiny matmuls (128 threads, 4-warp split) -------
__global__ __launch_bounds__(128) void pool_kernel(
    const float* __restrict__ x, const float* __restrict__ causal,
    const float* __restrict__ counter, const float* __restrict__ fcw,
    const float* __restrict__ fcb, float* __restrict__ out)
{
    __shared__ float part[4][3][DD];   // per-warp partial sums
    __shared__ float pv[3][DD];
    __shared__ float wsh[TT * DD];
    const int g = blockIdx.x, tid = threadIdx.x;
    const int w = tid >> 5, t = tid & 31;

    for (int j = tid; j < TT * DD; j += 128) wsh[j] = fcw[j];

    const float4* x4 = (const float4*)x;
    const float4* a4 = (const float4*)causal;
    const float4* c4 = (const float4*)counter;

    int s = g_seg[g], e = g_seg[g + 1];
    float4 sx = {0,0,0,0}, sa = {0,0,0,0}, sc = {0,0,0,0};
#pragma unroll 2
    for (int i = s + w; i < e; i += 4) {
        int k = g_idx[i];
        float4 vx = x4[(size_t)i * 32 + t];
        float4 va = a4[(size_t)k * 32 + t];
        float4 vc = c4[(size_t)k * 32 + t];
        sx.x += vx.x; sx.y += vx.y; sx.z += vx.z; sx.w += vx.w;
        sa.x += va.x; sa.y += va.y; sa.z += va.z; sa.w += va.w;
        sc.x += vc.x; sc.y += vc.y; sc.z += vc.z; sc.w += vc.w;
    }
    ((float4*)part[w][0])[t] = sx;
    ((float4*)part[w][1])[t] = sa;
    ((float4*)part[w][2])[t] = sc;
    __syncthreads();

    float fx = (part[0][0][tid] + part[1][0][tid]) + (part[2][0][tid] + part[3][0][tid]);
    float fa = (part[0][1][tid] + part[1][1][tid]) + (part[2][1][tid] + part[3][1][tid]);
    float fc = (part[0][2][tid] + part[1][2][tid]) + (part[2][2][tid] + part[3][2][tid]);

    float cnt = (float)(e - s);
    float inv = 1.f / fmaxf(cnt, 1.f);
    float px  = fx * inv;
    float pca = (fx + fa) * inv;
    float pco = fc * inv;

    out[OFF_PCA + (size_t)g * DD + tid] = pca;
    out[OFF_PX  + (size_t)g * DD + tid] = px;

    pv[0][tid] = pca; pv[1][tid] = pco; pv[2][tid] = px;
    __syncthreads();

    if (tid < 3 * TT) {
        int v = tid / TT, tk = tid % TT;
        float acc = fcb[tk];
#pragma unroll 8
        for (int q = 0; q < DD; ++q) acc = fmaf(pv[v][q], wsh[tk * DD + q], acc);
        out[(size_t)v * (GG * TT) + g * TT + tk] = acc;
    }
}

extern "C" void kernel_launch(void* const* d_in, const int* in_sizes, int n_in,
                              void* d_out, int out_size) {
    const float* x        = (const float*)d_in[0];
    const int*   batch    = (const int*)  d_in[1];
    const float* codebook = (const float*)d_in[2];
    const float* causal   = (const float*)d_in[3];
    const float* counter  = (const float*)d_in[4];
    const float* fcw      = (const float*)d_in[5];
    const float* fcb      = (const float*)d_in[6];
    float* out = (float*)d_out;

    cudaFuncSetAttribute(argmin_tc,
                         cudaFuncAttributeMaxDynamicSharedMemorySize, SMEM_TC);

    seg_kernel<<<(GG + 1 + 255) / 256, 256>>>(batch, NN);
    prep_kernel<<<KK / 8, 256>>>(causal);
    prep_split_kernel<<<4, 256>>>(causal);
    argmin_tc<<<NN / 256, 256, SMEM_TC>>>(x);
    x2pre_kernel<<<256, 128>>>(x);
    refine_kernel<<<256, 128>>>(x);
    gather_kernel<<<(NN * 32) / 256, 256>>>(codebook, out + OFF_Z);
    pool_kernel<<<GG, 128>>>(x, causal, counter, fcw, fcb, out);
}